// round 5
// baseline (speedup 1.0000x reference)
#include <cuda_runtime.h>
#include <mma.h>
#include <math.h>
#include <stdint.h>

using namespace nvcuda;

#define DIM   512
#define NHEAD 8
#define HD    64
#define FFN   2048
#define BB    4
#define TT    2048
#define ROWS  (BB*TT)     // 8192
#define CTX   64

// ---------------- scratch (allocation-free) ----------------
__device__ float g_xn  [ROWS * DIM];
__device__ float g_qkv [ROWS * 3 * DIM];
__device__ float g_attn[ROWS * DIM];
__device__ float g_x1  [ROWS * DIM];
__device__ float g_h   [ROWS * FFN];

// ================= cp.async helpers =================
__device__ __forceinline__ uint32_t smem_u32(const void* p) {
    uint32_t a;
    asm("{ .reg .u64 t; cvta.to.shared.u64 t, %1; cvt.u32.u64 %0, t; }" : "=r"(a) : "l"(p));
    return a;
}
__device__ __forceinline__ void cp_async16(uint32_t saddr, const void* gaddr) {
    asm volatile("cp.async.cg.shared.global [%0], [%1], 16;" :: "r"(saddr), "l"(gaddr));
}
#define CP_COMMIT() asm volatile("cp.async.commit_group;" ::: "memory")
#define CP_WAIT(n)  asm volatile("cp.async.wait_group %0;" :: "n"(n) : "memory")

// ================= RMSNorm =================
__global__ void __launch_bounds__(256) rmsnorm_kernel(
    const float* __restrict__ x, const float* __restrict__ w, float* __restrict__ y)
{
    int row = blockIdx.x;
    int t = threadIdx.x;
    const float* xr = x + (size_t)row * DIM;
    float v0 = xr[t], v1 = xr[t + 256];
    float s = v0 * v0 + v1 * v1;
    #pragma unroll
    for (int o = 16; o; o >>= 1) s += __shfl_xor_sync(0xffffffffu, s, o);
    __shared__ float red[8];
    if ((t & 31) == 0) red[t >> 5] = s;
    __syncthreads();
    if (t < 8) {
        float r = red[t];
        #pragma unroll
        for (int o = 4; o; o >>= 1) r += __shfl_xor_sync(0xffu, r, o);
        if (t == 0) red[0] = r;
    }
    __syncthreads();
    float inv = 1.0f / sqrtf(red[0] * (1.0f / DIM) + 1e-6f);
    float* yr = y + (size_t)row * DIM;
    yr[t]       = v0 * inv * w[t];
    yr[t + 256] = v1 * inv * w[t + 256];
}

// ================= wmma tf32 GEMM, cp.async pipelined =================
// C[M,N] = A[M,K] @ B[K,N], both row-major. CTA tile 128x128, 8 warps
// (warp tile 64x32 = 4x2 wmma m16n16k8). K chunks of 32, 3-stage cp.async.
// EPI: 0 plain, 1 bias+GELU, 2 bias+residual
#define KC      32
#define LDA     36
#define LDB     132
#define STAGES  3
#define A_STG   (128 * LDA)          // floats
#define B_STG   (KC * LDB)
#define STG_FL  (A_STG + B_STG)      // 8832 floats = 35328 B
#define LDST    136
#define GEMM_SMEM (STAGES * STG_FL * 4)   // 105984 B

template<int EPI>
__global__ void __launch_bounds__(256, 1) gemm_tf32_kernel(
    const float* __restrict__ A, const float* __restrict__ Bg,
    const float* __restrict__ bias, const float* __restrict__ res,
    float* __restrict__ C, int N, int K)
{
    extern __shared__ float sm[];
    uint32_t sm_base = smem_u32(sm);

    int tid = threadIdx.x;
    int wid = tid >> 5;
    int m0 = blockIdx.y * 128;
    int n0 = blockIdx.x * 128;
    int wm = wid >> 2;      // 0..1 -> 64 rows
    int wn = wid & 3;       // 0..3 -> 32 cols

    const int nc = K / KC;

    auto issue_chunk = [&](int ic) {
        uint32_t as_addr = sm_base + (uint32_t)((ic % STAGES) * STG_FL) * 4;
        uint32_t bs_addr = as_addr + A_STG * 4;
        #pragma unroll
        for (int i = 0; i < 4; i++) {
            int task = tid + i * 256;
            int r = task >> 3, sg = task & 7;
            cp_async16(as_addr + (uint32_t)(r * LDA + sg * 4) * 4,
                       A + (size_t)(m0 + r) * K + ic * KC + sg * 4);
        }
        #pragma unroll
        for (int i = 0; i < 4; i++) {
            int task = tid + i * 256;
            int r = task >> 5, sg = task & 31;
            cp_async16(bs_addr + (uint32_t)(r * LDB + sg * 4) * 4,
                       Bg + (size_t)(ic * KC + r) * N + n0 + sg * 4);
        }
    };

    wmma::fragment<wmma::accumulator, 16, 16, 8, float> acc[4][2];
    #pragma unroll
    for (int i = 0; i < 4; i++)
        #pragma unroll
        for (int j = 0; j < 2; j++)
            wmma::fill_fragment(acc[i][j], 0.0f);

    // prologue
    issue_chunk(0); CP_COMMIT();
    issue_chunk(1); CP_COMMIT();

    for (int ic = 0; ic < nc; ic++) {
        CP_WAIT(STAGES - 2);
        __syncthreads();
        if (ic + STAGES - 1 < nc) issue_chunk(ic + STAGES - 1);
        CP_COMMIT();

        float* As = sm + (ic % STAGES) * STG_FL;
        float* Bs = As + A_STG;
        #pragma unroll
        for (int ks = 0; ks < 4; ks++) {
            wmma::fragment<wmma::matrix_a, 16, 16, 8, wmma::precision::tf32, wmma::row_major> af[4];
            wmma::fragment<wmma::matrix_b, 16, 16, 8, wmma::precision::tf32, wmma::row_major> bf[2];
            #pragma unroll
            for (int i = 0; i < 4; i++) {
                wmma::load_matrix_sync(af[i], As + (size_t)(wm * 64 + i * 16) * LDA + ks * 8, LDA);
                #pragma unroll
                for (int t = 0; t < af[i].num_elements; t++)
                    af[i].x[t] = wmma::__float_to_tf32(af[i].x[t]);
            }
            #pragma unroll
            for (int j = 0; j < 2; j++) {
                wmma::load_matrix_sync(bf[j], Bs + (size_t)(ks * 8) * LDB + wn * 32 + j * 16, LDB);
                #pragma unroll
                for (int t = 0; t < bf[j].num_elements; t++)
                    bf[j].x[t] = wmma::__float_to_tf32(bf[j].x[t]);
            }
            #pragma unroll
            for (int i = 0; i < 4; i++)
                #pragma unroll
                for (int j = 0; j < 2; j++)
                    wmma::mma_sync(acc[i][j], af[i], bf[j], acc[i][j]);
        }
    }

    // ---- epilogue: acc -> smem stage -> coalesced fused STG ----
    __syncthreads();
    float* stage = sm;   // [128][LDST]
    #pragma unroll
    for (int i = 0; i < 4; i++)
        #pragma unroll
        for (int j = 0; j < 2; j++)
            wmma::store_matrix_sync(stage + (size_t)(wm * 64 + i * 16) * LDST + wn * 32 + j * 16,
                                    acc[i][j], LDST, wmma::mem_row_major);
    __syncthreads();

    #pragma unroll
    for (int jj = 0; jj < 16; jj++) {
        int idx = jj * 256 + tid;
        int m = idx >> 5, g = idx & 31;
        float4 v = *(float4*)(stage + (size_t)m * LDST + g * 4);
        int c = n0 + g * 4;
        if (EPI == 1) {
            float4 b = *(const float4*)(bias + c);
            v.x += b.x; v.y += b.y; v.z += b.z; v.w += b.w;
            v.x = 0.5f * v.x * (1.0f + erff(v.x * 0.70710678118654752f));
            v.y = 0.5f * v.y * (1.0f + erff(v.y * 0.70710678118654752f));
            v.z = 0.5f * v.z * (1.0f + erff(v.z * 0.70710678118654752f));
            v.w = 0.5f * v.w * (1.0f + erff(v.w * 0.70710678118654752f));
        } else if (EPI == 2) {
            float4 b = *(const float4*)(bias + c);
            float4 rr = *(const float4*)(res + (size_t)(m0 + m) * N + c);
            v.x += b.x + rr.x; v.y += b.y + rr.y;
            v.z += b.z + rr.z; v.w += b.w + rr.w;
        }
        *(float4*)(C + (size_t)(m0 + m) * N + c) = v;
    }
}

// ================= Banded attention (fp32) =================
#define Q_PAD 68
#define S_PAD 193
#define SMEM_FLOATS (64*Q_PAD + 192*Q_PAD + 192*Q_PAD + 64*S_PAD)

__global__ void __launch_bounds__(256) attn_kernel(
    const float* __restrict__ qkv, float* __restrict__ out)
{
    extern __shared__ float sm[];
    float* Qs = sm;
    float* Ks = Qs + 64 * Q_PAD;
    float* Vs = Ks + 192 * Q_PAD;
    float* Ss = Vs + 192 * Q_PAD;

    int tid = threadIdx.x;
    int qt = blockIdx.x, h = blockIdx.y, b = blockIdx.z;
    int q0 = qt * 64;
    int kbase = q0 - CTX;

    for (int idx = tid; idx < 64 * 16; idx += 256) {
        int r = idx >> 4, d4 = idx & 15;
        float4 v = *(const float4*)(qkv + ((size_t)(b * TT + q0 + r)) * (3 * DIM) + h * HD + d4 * 4);
        *(float4*)&Qs[r * Q_PAD + d4 * 4] = v;
    }
    for (int idx = tid; idx < 192 * 16; idx += 256) {
        int r = idx >> 4, d4 = idx & 15;
        int kg = kbase + r;
        float4 kv = {0.f, 0.f, 0.f, 0.f}, vv = {0.f, 0.f, 0.f, 0.f};
        if (kg >= 0 && kg < TT) {
            const float* base = qkv + ((size_t)(b * TT + kg)) * (3 * DIM) + h * HD + d4 * 4;
            kv = *(const float4*)(base + DIM);
            vv = *(const float4*)(base + 2 * DIM);
        }
        *(float4*)&Ks[r * Q_PAD + d4 * 4] = kv;
        *(float4*)&Vs[r * Q_PAD + d4 * 4] = vv;
    }
    __syncthreads();

    const float scale = 0.125f;
    for (int idx = tid; idx < 64 * 192; idx += 256) {
        int q = idx / 192, kk = idx - q * 192;
        int kg = kbase + kk;
        float s = -1e30f;
        if (kk >= q && kk <= q + 2 * CTX && kg >= 0 && kg < TT) {
            const float4* qp = (const float4*)&Qs[q * Q_PAD];
            const float4* kp = (const float4*)&Ks[kk * Q_PAD];
            float a0 = 0.f;
            #pragma unroll
            for (int d = 0; d < 16; d++) {
                float4 a = qp[d], c = kp[d];
                a0 += a.x * c.x + a.y * c.y + a.z * c.z + a.w * c.w;
            }
            s = a0 * scale;
        }
        Ss[q * S_PAD + kk] = s;
    }
    __syncthreads();

    {
        int q = tid >> 2, l = tid & 3;
        float mx = -1e30f;
        for (int kk = l; kk < 192; kk += 4) mx = fmaxf(mx, Ss[q * S_PAD + kk]);
        mx = fmaxf(mx, __shfl_xor_sync(0xffffffffu, mx, 1));
        mx = fmaxf(mx, __shfl_xor_sync(0xffffffffu, mx, 2));
        float sum = 0.f;
        for (int kk = l; kk < 192; kk += 4) {
            float s = Ss[q * S_PAD + kk];
            float e = (s > -1e29f) ? expf(s - mx) : 0.f;
            Ss[q * S_PAD + kk] = e;
            sum += e;
        }
        sum += __shfl_xor_sync(0xffffffffu, sum, 1);
        sum += __shfl_xor_sync(0xffffffffu, sum, 2);
        float inv = 1.f / sum;
        for (int kk = l; kk < 192; kk += 4) Ss[q * S_PAD + kk] *= inv;
    }
    __syncthreads();

    for (int idx = tid; idx < 64 * 16; idx += 256) {
        int q = idx >> 4, d4 = idx & 15;
        float4 acc = {0.f, 0.f, 0.f, 0.f};
        int kkend = q + 2 * CTX + 1;
        for (int kk = q; kk < kkend; kk++) {
            float p = Ss[q * S_PAD + kk];
            float4 v = *(const float4*)&Vs[kk * Q_PAD + d4 * 4];
            acc.x += p * v.x; acc.y += p * v.y; acc.z += p * v.z; acc.w += p * v.w;
        }
        *(float4*)(out + ((size_t)(b * TT + q0 + q)) * DIM + h * HD + d4 * 4) = acc;
    }
}

// ================= launcher =================
extern "C" void kernel_launch(void* const* d_in, const int* in_sizes, int n_in,
                              void* d_out, int out_size)
{
    const float* x       = (const float*)d_in[0];
    const float* norm1_w = (const float*)d_in[1];
    const float* norm2_w = (const float*)d_in[2];
    const float* w_qkv   = (const float*)d_in[3];
    const float* w_out   = (const float*)d_in[4];
    const float* b_out   = (const float*)d_in[5];
    const float* w1      = (const float*)d_in[6];
    const float* b1      = (const float*)d_in[7];
    const float* w2      = (const float*)d_in[8];
    const float* b2      = (const float*)d_in[9];
    float* y = (float*)d_out;

    float *xn, *qkv, *attn, *x1, *hbuf;
    cudaGetSymbolAddress((void**)&xn,   g_xn);
    cudaGetSymbolAddress((void**)&qkv,  g_qkv);
    cudaGetSymbolAddress((void**)&attn, g_attn);
    cudaGetSymbolAddress((void**)&x1,   g_x1);
    cudaGetSymbolAddress((void**)&hbuf, g_h);

    static_assert(SMEM_FLOATS * 4 <= 227 * 1024, "smem");
    cudaFuncSetAttribute(attn_kernel, cudaFuncAttributeMaxDynamicSharedMemorySize,
                         SMEM_FLOATS * 4);
    cudaFuncSetAttribute(gemm_tf32_kernel<0>, cudaFuncAttributeMaxDynamicSharedMemorySize, GEMM_SMEM);
    cudaFuncSetAttribute(gemm_tf32_kernel<1>, cudaFuncAttributeMaxDynamicSharedMemorySize, GEMM_SMEM);
    cudaFuncSetAttribute(gemm_tf32_kernel<2>, cudaFuncAttributeMaxDynamicSharedMemorySize, GEMM_SMEM);

    // 1. rmsnorm(x) -> xn
    rmsnorm_kernel<<<ROWS, 256>>>(x, norm1_w, xn);
    // 2. qkv = xn @ w_qkv
    gemm_tf32_kernel<0><<<dim3((3 * DIM) / 128, ROWS / 128), 256, GEMM_SMEM>>>(
        xn, w_qkv, nullptr, nullptr, qkv, 3 * DIM, DIM);
    // 3. banded attention
    attn_kernel<<<dim3(TT / 64, NHEAD, BB), 256, SMEM_FLOATS * 4>>>(qkv, attn);
    // 4. x1 = x + attn @ w_out + b_out
    gemm_tf32_kernel<2><<<dim3(DIM / 128, ROWS / 128), 256, GEMM_SMEM>>>(
        attn, w_out, b_out, x, x1, DIM, DIM);
    // 5. rmsnorm(x1) -> xn
    rmsnorm_kernel<<<ROWS, 256>>>(x1, norm2_w, xn);
    // 6. h = gelu(xn @ w1 + b1)
    gemm_tf32_kernel<1><<<dim3(FFN / 128, ROWS / 128), 256, GEMM_SMEM>>>(
        xn, w1, b1, nullptr, hbuf, FFN, DIM);
    // 7. y = x1 + h @ w2 + b2
    gemm_tf32_kernel<2><<<dim3(DIM / 128, ROWS / 128), 256, GEMM_SMEM>>>(
        hbuf, w2, b2, x1, y, DIM, FFN);
}

// round 6
// speedup vs baseline: 1.1558x; 1.1558x over previous
#include <cuda_runtime.h>
#include <mma.h>
#include <math.h>
#include <stdint.h>

using namespace nvcuda;

#define DIM   512
#define NHEAD 8
#define HD    64
#define FFN   2048
#define BB    4
#define TT    2048
#define ROWS  (BB*TT)     // 8192
#define CTX   64

// ---------------- scratch (allocation-free) ----------------
__device__ float g_xn  [ROWS * DIM];
__device__ float g_qkv [ROWS * 3 * DIM];
__device__ float g_attn[ROWS * DIM];
__device__ float g_x1  [ROWS * DIM];
__device__ float g_h   [ROWS * FFN];
// tf32-pre-rounded weights
#define WQKV_OFF 0
#define WOUT_OFF (3 * DIM * DIM)
#define W1_OFF   (WOUT_OFF + DIM * DIM)
#define W2_OFF   (W1_OFF + DIM * FFN)
#define WTOT     (W2_OFF + FFN * DIM)
__device__ float g_wr[WTOT];

// ================= helpers =================
__device__ __forceinline__ uint32_t smem_u32(const void* p) {
    uint32_t a;
    asm("{ .reg .u64 t; cvta.to.shared.u64 t, %1; cvt.u32.u64 %0, t; }" : "=r"(a) : "l"(p));
    return a;
}
__device__ __forceinline__ void cp_async16(uint32_t saddr, const void* gaddr) {
    asm volatile("cp.async.cg.shared.global [%0], [%1], 16;" :: "r"(saddr), "l"(gaddr));
}
#define CP_COMMIT() asm volatile("cp.async.commit_group;" ::: "memory")
#define CP_WAIT(n)  asm volatile("cp.async.wait_group %0;" :: "n"(n) : "memory")

__device__ __forceinline__ float rtf32(float f) {
    uint32_t r;
    asm("cvt.rna.tf32.f32 %0, %1;" : "=r"(r) : "f"(f));
    return __uint_as_float(r);
}

// elementwise tf32-round copy (for weights)
__global__ void __launch_bounds__(256) round_tf32_kernel(
    const float* __restrict__ in, float* __restrict__ out, int n4)
{
    int i = blockIdx.x * 256 + threadIdx.x;
    if (i < n4) {
        float4 v = ((const float4*)in)[i];
        v.x = rtf32(v.x); v.y = rtf32(v.y); v.z = rtf32(v.z); v.w = rtf32(v.w);
        ((float4*)out)[i] = v;
    }
}

// ================= RMSNorm (tf32-rounded output) =================
__global__ void __launch_bounds__(256) rmsnorm_kernel(
    const float* __restrict__ x, const float* __restrict__ w, float* __restrict__ y)
{
    int row = blockIdx.x;
    int t = threadIdx.x;
    const float* xr = x + (size_t)row * DIM;
    float v0 = xr[t], v1 = xr[t + 256];
    float s = v0 * v0 + v1 * v1;
    #pragma unroll
    for (int o = 16; o; o >>= 1) s += __shfl_xor_sync(0xffffffffu, s, o);
    __shared__ float red[8];
    if ((t & 31) == 0) red[t >> 5] = s;
    __syncthreads();
    if (t < 8) {
        float r = red[t];
        #pragma unroll
        for (int o = 4; o; o >>= 1) r += __shfl_xor_sync(0xffu, r, o);
        if (t == 0) red[0] = r;
    }
    __syncthreads();
    float inv = 1.0f / sqrtf(red[0] * (1.0f / DIM) + 1e-6f);
    float* yr = y + (size_t)row * DIM;
    yr[t]       = rtf32(v0 * inv * w[t]);
    yr[t + 256] = rtf32(v1 * inv * w[t + 256]);
}

// ================= wmma tf32 GEMM, cp.async pipelined =================
// C[M,N] = A[M,K] @ B[K,N], row-major, inputs pre-rounded to tf32.
// CTA tile 128x128, 4 warps (warp tile 64x64 = 4x4 wmma m16n16k8).
// K chunks of 32, 2-stage cp.async, 2 CTAs/SM.
// EPI: 0 plain, 1 bias+GELU (rounded out), 2 bias+residual
#define KC      32
#define LDA     36
#define LDB     132
#define STAGES  2
#define A_STG   (128 * LDA)          // floats
#define B_STG   (KC * LDB)
#define STG_FL  (A_STG + B_STG)      // 8832 floats = 35328 B
#define LDST    136
#define GEMM_SMEM (STAGES * STG_FL * 4)   // 70656 B

template<int EPI>
__global__ void __launch_bounds__(128, 2) gemm_tf32_kernel(
    const float* __restrict__ A, const float* __restrict__ Bg,
    const float* __restrict__ bias, const float* __restrict__ res,
    float* __restrict__ C, int N, int K)
{
    extern __shared__ float sm[];
    uint32_t sm_base = smem_u32(sm);

    int tid = threadIdx.x;
    int wid = tid >> 5;
    int m0 = blockIdx.y * 128;
    int n0 = blockIdx.x * 128;
    int wm = wid >> 1;      // 0..1 -> 64 rows
    int wn = wid & 1;       // 0..1 -> 64 cols

    const int nc = K / KC;

    auto issue_chunk = [&](int ic) {
        uint32_t as_addr = sm_base + (uint32_t)((ic & 1) * STG_FL) * 4;
        uint32_t bs_addr = as_addr + A_STG * 4;
        #pragma unroll
        for (int i = 0; i < 8; i++) {
            int task = tid + i * 128;
            int r = task >> 3, sg = task & 7;
            cp_async16(as_addr + (uint32_t)(r * LDA + sg * 4) * 4,
                       A + (size_t)(m0 + r) * K + ic * KC + sg * 4);
        }
        #pragma unroll
        for (int i = 0; i < 8; i++) {
            int task = tid + i * 128;
            int r = task >> 5, sg = task & 31;
            cp_async16(bs_addr + (uint32_t)(r * LDB + sg * 4) * 4,
                       Bg + (size_t)(ic * KC + r) * N + n0 + sg * 4);
        }
    };

    wmma::fragment<wmma::accumulator, 16, 16, 8, float> acc[4][4];
    #pragma unroll
    for (int i = 0; i < 4; i++)
        #pragma unroll
        for (int j = 0; j < 4; j++)
            wmma::fill_fragment(acc[i][j], 0.0f);

    issue_chunk(0); CP_COMMIT();

    for (int ic = 0; ic < nc; ic++) {
        if (ic + 1 < nc) { issue_chunk(ic + 1); CP_COMMIT(); CP_WAIT(1); }
        else             { CP_WAIT(0); }
        __syncthreads();

        float* As = sm + (ic & 1) * STG_FL;
        float* Bs = As + A_STG;
        #pragma unroll
        for (int ks = 0; ks < 4; ks++) {
            wmma::fragment<wmma::matrix_a, 16, 16, 8, wmma::precision::tf32, wmma::row_major> af[4];
            wmma::fragment<wmma::matrix_b, 16, 16, 8, wmma::precision::tf32, wmma::row_major> bf[4];
            #pragma unroll
            for (int i = 0; i < 4; i++)
                wmma::load_matrix_sync(af[i], As + (size_t)(wm * 64 + i * 16) * LDA + ks * 8, LDA);
            #pragma unroll
            for (int j = 0; j < 4; j++)
                wmma::load_matrix_sync(bf[j], Bs + (size_t)(ks * 8) * LDB + wn * 64 + j * 16, LDB);
            #pragma unroll
            for (int i = 0; i < 4; i++)
                #pragma unroll
                for (int j = 0; j < 4; j++)
                    wmma::mma_sync(acc[i][j], af[i], bf[j], acc[i][j]);
        }
        __syncthreads();
    }

    // ---- epilogue: acc -> smem stage -> coalesced fused STG ----
    float* stage = sm;   // [128][LDST] = 69632 B <= 70656
    #pragma unroll
    for (int i = 0; i < 4; i++)
        #pragma unroll
        for (int j = 0; j < 4; j++)
            wmma::store_matrix_sync(stage + (size_t)(wm * 64 + i * 16) * LDST + wn * 64 + j * 16,
                                    acc[i][j], LDST, wmma::mem_row_major);
    __syncthreads();

    #pragma unroll
    for (int jj = 0; jj < 32; jj++) {
        int idx = jj * 128 + tid;
        int m = idx >> 5, g = idx & 31;
        float4 v = *(float4*)(stage + (size_t)m * LDST + g * 4);
        int c = n0 + g * 4;
        if (EPI == 1) {
            float4 b = *(const float4*)(bias + c);
            v.x += b.x; v.y += b.y; v.z += b.z; v.w += b.w;
            v.x = rtf32(0.5f * v.x * (1.0f + erff(v.x * 0.70710678118654752f)));
            v.y = rtf32(0.5f * v.y * (1.0f + erff(v.y * 0.70710678118654752f)));
            v.z = rtf32(0.5f * v.z * (1.0f + erff(v.z * 0.70710678118654752f)));
            v.w = rtf32(0.5f * v.w * (1.0f + erff(v.w * 0.70710678118654752f)));
        } else if (EPI == 2) {
            float4 b = *(const float4*)(bias + c);
            float4 rr = *(const float4*)(res + (size_t)(m0 + m) * N + c);
            v.x += b.x + rr.x; v.y += b.y + rr.y;
            v.z += b.z + rr.z; v.w += b.w + rr.w;
        }
        *(float4*)(C + (size_t)(m0 + m) * N + c) = v;
    }
}

// ================= Banded attention (fp32, tf32-rounded output) =================
#define Q_PAD 68
#define S_PAD 193
#define SMEM_FLOATS (64*Q_PAD + 192*Q_PAD + 192*Q_PAD + 64*S_PAD)

__global__ void __launch_bounds__(256) attn_kernel(
    const float* __restrict__ qkv, float* __restrict__ out)
{
    extern __shared__ float sm[];
    float* Qs = sm;
    float* Ks = Qs + 64 * Q_PAD;
    float* Vs = Ks + 192 * Q_PAD;
    float* Ss = Vs + 192 * Q_PAD;

    int tid = threadIdx.x;
    int qt = blockIdx.x, h = blockIdx.y, b = blockIdx.z;
    int q0 = qt * 64;
    int kbase = q0 - CTX;

    for (int idx = tid; idx < 64 * 16; idx += 256) {
        int r = idx >> 4, d4 = idx & 15;
        float4 v = *(const float4*)(qkv + ((size_t)(b * TT + q0 + r)) * (3 * DIM) + h * HD + d4 * 4);
        *(float4*)&Qs[r * Q_PAD + d4 * 4] = v;
    }
    for (int idx = tid; idx < 192 * 16; idx += 256) {
        int r = idx >> 4, d4 = idx & 15;
        int kg = kbase + r;
        float4 kv = {0.f, 0.f, 0.f, 0.f}, vv = {0.f, 0.f, 0.f, 0.f};
        if (kg >= 0 && kg < TT) {
            const float* base = qkv + ((size_t)(b * TT + kg)) * (3 * DIM) + h * HD + d4 * 4;
            kv = *(const float4*)(base + DIM);
            vv = *(const float4*)(base + 2 * DIM);
        }
        *(float4*)&Ks[r * Q_PAD + d4 * 4] = kv;
        *(float4*)&Vs[r * Q_PAD + d4 * 4] = vv;
    }
    __syncthreads();

    const float scale = 0.125f;
    for (int idx = tid; idx < 64 * 192; idx += 256) {
        int q = idx / 192, kk = idx - q * 192;
        int kg = kbase + kk;
        float s = -1e30f;
        if (kk >= q && kk <= q + 2 * CTX && kg >= 0 && kg < TT) {
            const float4* qp = (const float4*)&Qs[q * Q_PAD];
            const float4* kp = (const float4*)&Ks[kk * Q_PAD];
            float a0 = 0.f;
            #pragma unroll
            for (int d = 0; d < 16; d++) {
                float4 a = qp[d], c = kp[d];
                a0 += a.x * c.x + a.y * c.y + a.z * c.z + a.w * c.w;
            }
            s = a0 * scale;
        }
        Ss[q * S_PAD + kk] = s;
    }
    __syncthreads();

    {
        int q = tid >> 2, l = tid & 3;
        float mx = -1e30f;
        for (int kk = l; kk < 192; kk += 4) mx = fmaxf(mx, Ss[q * S_PAD + kk]);
        mx = fmaxf(mx, __shfl_xor_sync(0xffffffffu, mx, 1));
        mx = fmaxf(mx, __shfl_xor_sync(0xffffffffu, mx, 2));
        float sum = 0.f;
        for (int kk = l; kk < 192; kk += 4) {
            float s = Ss[q * S_PAD + kk];
            float e = (s > -1e29f) ? expf(s - mx) : 0.f;
            Ss[q * S_PAD + kk] = e;
            sum += e;
        }
        sum += __shfl_xor_sync(0xffffffffu, sum, 1);
        sum += __shfl_xor_sync(0xffffffffu, sum, 2);
        float inv = 1.f / sum;
        for (int kk = l; kk < 192; kk += 4) Ss[q * S_PAD + kk] *= inv;
    }
    __syncthreads();

    for (int idx = tid; idx < 64 * 16; idx += 256) {
        int q = idx >> 4, d4 = idx & 15;
        float4 acc = {0.f, 0.f, 0.f, 0.f};
        int kkend = q + 2 * CTX + 1;
        for (int kk = q; kk < kkend; kk++) {
            float p = Ss[q * S_PAD + kk];
            float4 v = *(const float4*)&Vs[kk * Q_PAD + d4 * 4];
            acc.x += p * v.x; acc.y += p * v.y; acc.z += p * v.z; acc.w += p * v.w;
        }
        acc.x = rtf32(acc.x); acc.y = rtf32(acc.y);
        acc.z = rtf32(acc.z); acc.w = rtf32(acc.w);
        *(float4*)(out + ((size_t)(b * TT + q0 + q)) * DIM + h * HD + d4 * 4) = acc;
    }
}

// ================= launcher =================
extern "C" void kernel_launch(void* const* d_in, const int* in_sizes, int n_in,
                              void* d_out, int out_size)
{
    const float* x       = (const float*)d_in[0];
    const float* norm1_w = (const float*)d_in[1];
    const float* norm2_w = (const float*)d_in[2];
    const float* w_qkv   = (const float*)d_in[3];
    const float* w_out   = (const float*)d_in[4];
    const float* b_out   = (const float*)d_in[5];
    const float* w1      = (const float*)d_in[6];
    const float* b1      = (const float*)d_in[7];
    const float* w2      = (const float*)d_in[8];
    const float* b2      = (const float*)d_in[9];
    float* y = (float*)d_out;

    float *xn, *qkv, *attn, *x1, *hbuf, *wr;
    cudaGetSymbolAddress((void**)&xn,   g_xn);
    cudaGetSymbolAddress((void**)&qkv,  g_qkv);
    cudaGetSymbolAddress((void**)&attn, g_attn);
    cudaGetSymbolAddress((void**)&x1,   g_x1);
    cudaGetSymbolAddress((void**)&hbuf, g_h);
    cudaGetSymbolAddress((void**)&wr,   g_wr);

    static_assert(SMEM_FLOATS * 4 <= 227 * 1024, "smem");
    cudaFuncSetAttribute(attn_kernel, cudaFuncAttributeMaxDynamicSharedMemorySize,
                         SMEM_FLOATS * 4);
    cudaFuncSetAttribute(gemm_tf32_kernel<0>, cudaFuncAttributeMaxDynamicSharedMemorySize, GEMM_SMEM);
    cudaFuncSetAttribute(gemm_tf32_kernel<1>, cudaFuncAttributeMaxDynamicSharedMemorySize, GEMM_SMEM);
    cudaFuncSetAttribute(gemm_tf32_kernel<2>, cudaFuncAttributeMaxDynamicSharedMemorySize, GEMM_SMEM);

    // 0. pre-round weights to tf32
    round_tf32_kernel<<<(3 * DIM * DIM / 4 + 255) / 256, 256>>>(w_qkv, wr + WQKV_OFF, 3 * DIM * DIM / 4);
    round_tf32_kernel<<<(DIM * DIM / 4 + 255) / 256, 256>>>(w_out, wr + WOUT_OFF, DIM * DIM / 4);
    round_tf32_kernel<<<(DIM * FFN / 4 + 255) / 256, 256>>>(w1, wr + W1_OFF, DIM * FFN / 4);
    round_tf32_kernel<<<(FFN * DIM / 4 + 255) / 256, 256>>>(w2, wr + W2_OFF, FFN * DIM / 4);

    // 1. rmsnorm(x) -> xn (tf32)
    rmsnorm_kernel<<<ROWS, 256>>>(x, norm1_w, xn);
    // 2. qkv = xn @ w_qkv
    gemm_tf32_kernel<0><<<dim3((3 * DIM) / 128, ROWS / 128), 128, GEMM_SMEM>>>(
        xn, wr + WQKV_OFF, nullptr, nullptr, qkv, 3 * DIM, DIM);
    // 3. banded attention -> attn (tf32)
    attn_kernel<<<dim3(TT / 64, NHEAD, BB), 256, SMEM_FLOATS * 4>>>(qkv, attn);
    // 4. x1 = x + attn @ w_out + b_out
    gemm_tf32_kernel<2><<<dim3(DIM / 128, ROWS / 128), 128, GEMM_SMEM>>>(
        attn, wr + WOUT_OFF, b_out, x, x1, DIM, DIM);
    // 5. rmsnorm(x1) -> xn (tf32)
    rmsnorm_kernel<<<ROWS, 256>>>(x1, norm2_w, xn);
    // 6. h = gelu(xn @ w1 + b1) (tf32)
    gemm_tf32_kernel<1><<<dim3(FFN / 128, ROWS / 128), 128, GEMM_SMEM>>>(
        xn, wr + W1_OFF, b1, nullptr, hbuf, FFN, DIM);
    // 7. y = x1 + h @ w2 + b2
    gemm_tf32_kernel<2><<<dim3(DIM / 128, ROWS / 128), 128, GEMM_SMEM>>>(
        hbuf, wr + W2_OFF, b2, x1, y, DIM, FFN);
}

// round 7
// speedup vs baseline: 2.4742x; 2.1407x over previous
#include <cuda_runtime.h>
#include <cuda_fp16.h>
#include <mma.h>
#include <math.h>
#include <stdint.h>

using namespace nvcuda;

#define DIM   512
#define NHEAD 8
#define HD    64
#define FFN   2048
#define BB    4
#define TT    2048
#define ROWS  (BB*TT)     // 8192
#define CTX   64

// ---------------- scratch (allocation-free) ----------------
__device__ __half g_xn_h  [ROWS * DIM];
__device__ __half g_qkv_h [ROWS * 3 * DIM];
__device__ __half g_attn_h[ROWS * DIM];
__device__ __half g_hbuf_h[ROWS * FFN];
__device__ float  g_x1    [ROWS * DIM];
// fp16 weights
#define WQKV_OFF 0
#define WOUT_OFF (3 * DIM * DIM)
#define W1_OFF   (WOUT_OFF + DIM * DIM)
#define W2_OFF   (W1_OFF + DIM * FFN)
#define WTOT     (W2_OFF + FFN * DIM)
__device__ __half g_w_h[WTOT];

// ================= helpers =================
__device__ __forceinline__ uint32_t smem_u32(const void* p) {
    uint32_t a;
    asm("{ .reg .u64 t; cvta.to.shared.u64 t, %1; cvt.u32.u64 %0, t; }" : "=r"(a) : "l"(p));
    return a;
}
__device__ __forceinline__ void cp_async16(uint32_t saddr, const void* gaddr) {
    asm volatile("cp.async.cg.shared.global [%0], [%1], 16;" :: "r"(saddr), "l"(gaddr));
}
#define CP_COMMIT() asm volatile("cp.async.commit_group;" ::: "memory")
#define CP_WAIT(n)  asm volatile("cp.async.wait_group %0;" :: "n"(n) : "memory")

// fp32 -> fp16 convert (weights)
__global__ void __launch_bounds__(256) f2h_kernel(
    const float* __restrict__ in, __half* __restrict__ out, int n4)
{
    int i = blockIdx.x * 256 + threadIdx.x;
    if (i < n4) {
        float4 v = ((const float4*)in)[i];
        __half2 h0 = __floats2half2_rn(v.x, v.y);
        __half2 h1 = __floats2half2_rn(v.z, v.w);
        ((__half2*)out)[i * 2]     = h0;
        ((__half2*)out)[i * 2 + 1] = h1;
    }
}

// ================= RMSNorm (half output) =================
__global__ void __launch_bounds__(256) rmsnorm_kernel(
    const float* __restrict__ x, const float* __restrict__ w, __half* __restrict__ y)
{
    int row = blockIdx.x;
    int t = threadIdx.x;
    const float* xr = x + (size_t)row * DIM;
    float v0 = xr[t], v1 = xr[t + 256];
    float s = v0 * v0 + v1 * v1;
    #pragma unroll
    for (int o = 16; o; o >>= 1) s += __shfl_xor_sync(0xffffffffu, s, o);
    __shared__ float red[8];
    if ((t & 31) == 0) red[t >> 5] = s;
    __syncthreads();
    if (t < 8) {
        float r = red[t];
        #pragma unroll
        for (int o = 4; o; o >>= 1) r += __shfl_xor_sync(0xffu, r, o);
        if (t == 0) red[0] = r;
    }
    __syncthreads();
    float inv = 1.0f / sqrtf(red[0] * (1.0f / DIM) + 1e-6f);
    __half* yr = y + (size_t)row * DIM;
    yr[t]       = __float2half_rn(v0 * inv * w[t]);
    yr[t + 256] = __float2half_rn(v1 * inv * w[t + 256]);
}

// ================= wmma fp16 GEMM, cp.async pipelined =================
// C[M,N] = A[M,K] @ B[K,N], half inputs row-major, fp32 accum.
// CTA tile 128x128, 4 warps (warp tile 64x64 = 4x4 wmma m16n16k16).
// K chunks of 64 (4 k-steps), 2-stage cp.async, 2 CTAs/SM.
// EPI: 0 plain (half out), 1 bias+GELU (half out), 2 bias+residual (float out)
#define KC     64
#define LDA    72          // halves (KC + 8)
#define LDB    144         // halves (128 + 16)
#define A_STG_H (128 * LDA)     // halves
#define B_STG_H (KC * LDB)
#define STG_H   (A_STG_H + B_STG_H)   // 18432 halves = 36864 B
#define LDST    136
#define GEMM_SMEM (2 * STG_H * 2)     // 73728 B

template<int EPI>
__global__ void __launch_bounds__(128, 2) gemm_h_kernel(
    const __half* __restrict__ A, const __half* __restrict__ Bg,
    const float* __restrict__ bias, const float* __restrict__ res,
    void* __restrict__ Cv, int N, int K)
{
    extern __shared__ char smraw[];
    __half* smh = (__half*)smraw;
    uint32_t sm_base = smem_u32(smraw);

    int tid = threadIdx.x;
    int wid = tid >> 5;
    int m0 = blockIdx.y * 128;
    int n0 = blockIdx.x * 128;
    int wm = wid >> 1;      // 0..1 -> 64 rows
    int wn = wid & 1;       // 0..1 -> 64 cols

    const int nc = K / KC;

    auto issue_chunk = [&](int ic) {
        uint32_t as_addr = sm_base + (uint32_t)((ic & 1) * STG_H) * 2;
        uint32_t bs_addr = as_addr + A_STG_H * 2;
        // A: 128 rows x 64 halves = 8 segs of 8 halves (16B) per row -> 1024 tasks
        #pragma unroll
        for (int i = 0; i < 8; i++) {
            int task = tid + i * 128;
            int r = task >> 3, sg = task & 7;
            cp_async16(as_addr + (uint32_t)(r * LDA + sg * 8) * 2,
                       A + (size_t)(m0 + r) * K + ic * KC + sg * 8);
        }
        // B: 64 rows x 128 halves = 16 segs per row -> 1024 tasks
        #pragma unroll
        for (int i = 0; i < 8; i++) {
            int task = tid + i * 128;
            int r = task >> 4, sg = task & 15;
            cp_async16(bs_addr + (uint32_t)(r * LDB + sg * 8) * 2,
                       Bg + (size_t)(ic * KC + r) * N + n0 + sg * 8);
        }
    };

    wmma::fragment<wmma::accumulator, 16, 16, 16, float> acc[4][4];
    #pragma unroll
    for (int i = 0; i < 4; i++)
        #pragma unroll
        for (int j = 0; j < 4; j++)
            wmma::fill_fragment(acc[i][j], 0.0f);

    issue_chunk(0); CP_COMMIT();

    for (int ic = 0; ic < nc; ic++) {
        if (ic + 1 < nc) { issue_chunk(ic + 1); CP_COMMIT(); CP_WAIT(1); }
        else             { CP_WAIT(0); }
        __syncthreads();

        __half* As = smh + (ic & 1) * STG_H;
        __half* Bs = As + A_STG_H;
        #pragma unroll
        for (int ks = 0; ks < 4; ks++) {
            wmma::fragment<wmma::matrix_a, 16, 16, 16, __half, wmma::row_major> af[4];
            wmma::fragment<wmma::matrix_b, 16, 16, 16, __half, wmma::row_major> bf[4];
            #pragma unroll
            for (int i = 0; i < 4; i++)
                wmma::load_matrix_sync(af[i], As + (size_t)(wm * 64 + i * 16) * LDA + ks * 16, LDA);
            #pragma unroll
            for (int j = 0; j < 4; j++)
                wmma::load_matrix_sync(bf[j], Bs + (size_t)(ks * 16) * LDB + wn * 64 + j * 16, LDB);
            #pragma unroll
            for (int i = 0; i < 4; i++)
                #pragma unroll
                for (int j = 0; j < 4; j++)
                    wmma::mma_sync(acc[i][j], af[i], bf[j], acc[i][j]);
        }
        __syncthreads();
    }

    // ---- epilogue: acc -> fp32 smem stage -> coalesced fused STG ----
    float* stage = (float*)smraw;   // [128][LDST] = 69632 B <= 73728
    #pragma unroll
    for (int i = 0; i < 4; i++)
        #pragma unroll
        for (int j = 0; j < 4; j++)
            wmma::store_matrix_sync(stage + (size_t)(wm * 64 + i * 16) * LDST + wn * 64 + j * 16,
                                    acc[i][j], LDST, wmma::mem_row_major);
    __syncthreads();

    #pragma unroll
    for (int jj = 0; jj < 32; jj++) {
        int idx = jj * 128 + tid;
        int m = idx >> 5, g = idx & 31;
        float4 v = *(float4*)(stage + (size_t)m * LDST + g * 4);
        int c = n0 + g * 4;
        if (EPI == 2) {
            float4 b = *(const float4*)(bias + c);
            float4 rr = *(const float4*)(res + (size_t)(m0 + m) * N + c);
            v.x += b.x + rr.x; v.y += b.y + rr.y;
            v.z += b.z + rr.z; v.w += b.w + rr.w;
            *(float4*)((float*)Cv + (size_t)(m0 + m) * N + c) = v;
        } else {
            if (EPI == 1) {
                float4 b = *(const float4*)(bias + c);
                v.x += b.x; v.y += b.y; v.z += b.z; v.w += b.w;
                v.x = 0.5f * v.x * (1.0f + erff(v.x * 0.70710678118654752f));
                v.y = 0.5f * v.y * (1.0f + erff(v.y * 0.70710678118654752f));
                v.z = 0.5f * v.z * (1.0f + erff(v.z * 0.70710678118654752f));
                v.w = 0.5f * v.w * (1.0f + erff(v.w * 0.70710678118654752f));
            }
            __half2 h0 = __floats2half2_rn(v.x, v.y);
            __half2 h1 = __floats2half2_rn(v.z, v.w);
            __half2* p = (__half2*)((__half*)Cv + (size_t)(m0 + m) * N + c);
            p[0] = h0; p[1] = h1;
        }
    }
}

// ================= Banded attention (half in/out, fp32 math) =================
#define Q_PAD 68
#define S_PAD 193
#define SMEM_FLOATS (64*Q_PAD + 192*Q_PAD + 192*Q_PAD + 64*S_PAD)

__device__ __forceinline__ void h8_to_f8(const __half* src, float* dst) {
    uint4 u = *(const uint4*)src;
    __half2* hp = (__half2*)&u;
    float2 f0 = __half22float2(hp[0]);
    float2 f1 = __half22float2(hp[1]);
    float2 f2 = __half22float2(hp[2]);
    float2 f3 = __half22float2(hp[3]);
    dst[0] = f0.x; dst[1] = f0.y; dst[2] = f1.x; dst[3] = f1.y;
    dst[4] = f2.x; dst[5] = f2.y; dst[6] = f3.x; dst[7] = f3.y;
}

__global__ void __launch_bounds__(256) attn_kernel(
    const __half* __restrict__ qkv, __half* __restrict__ out)
{
    extern __shared__ float sm[];
    float* Qs = sm;
    float* Ks = Qs + 64 * Q_PAD;
    float* Vs = Ks + 192 * Q_PAD;
    float* Ss = Vs + 192 * Q_PAD;

    int tid = threadIdx.x;
    int qt = blockIdx.x, h = blockIdx.y, b = blockIdx.z;
    int q0 = qt * 64;
    int kbase = q0 - CTX;

    // load Q (64 rows x 8 h8-groups)
    for (int idx = tid; idx < 64 * 8; idx += 256) {
        int r = idx >> 3, d8 = idx & 7;
        float f[8];
        h8_to_f8(qkv + ((size_t)(b * TT + q0 + r)) * (3 * DIM) + h * HD + d8 * 8, f);
        #pragma unroll
        for (int u = 0; u < 8; u++) Qs[r * Q_PAD + d8 * 8 + u] = f[u];
    }
    // load K,V (192 rows x 8 h8-groups)
    for (int idx = tid; idx < 192 * 8; idx += 256) {
        int r = idx >> 3, d8 = idx & 7;
        int kg = kbase + r;
        float fk[8] = {}, fv[8] = {};
        if (kg >= 0 && kg < TT) {
            const __half* base = qkv + ((size_t)(b * TT + kg)) * (3 * DIM) + h * HD + d8 * 8;
            h8_to_f8(base + DIM, fk);
            h8_to_f8(base + 2 * DIM, fv);
        }
        #pragma unroll
        for (int u = 0; u < 8; u++) {
            Ks[r * Q_PAD + d8 * 8 + u] = fk[u];
            Vs[r * Q_PAD + d8 * 8 + u] = fv[u];
        }
    }
    __syncthreads();

    const float scale = 0.125f;
    for (int idx = tid; idx < 64 * 192; idx += 256) {
        int q = idx / 192, kk = idx - q * 192;
        int kg = kbase + kk;
        float s = -1e30f;
        if (kk >= q && kk <= q + 2 * CTX && kg >= 0 && kg < TT) {
            const float4* qp = (const float4*)&Qs[q * Q_PAD];
            const float4* kp = (const float4*)&Ks[kk * Q_PAD];
            float a0 = 0.f;
            #pragma unroll
            for (int d = 0; d < 16; d++) {
                float4 a = qp[d], c = kp[d];
                a0 += a.x * c.x + a.y * c.y + a.z * c.z + a.w * c.w;
            }
            s = a0 * scale;
        }
        Ss[q * S_PAD + kk] = s;
    }
    __syncthreads();

    {
        int q = tid >> 2, l = tid & 3;
        float mx = -1e30f;
        for (int kk = l; kk < 192; kk += 4) mx = fmaxf(mx, Ss[q * S_PAD + kk]);
        mx = fmaxf(mx, __shfl_xor_sync(0xffffffffu, mx, 1));
        mx = fmaxf(mx, __shfl_xor_sync(0xffffffffu, mx, 2));
        float sum = 0.f;
        for (int kk = l; kk < 192; kk += 4) {
            float s = Ss[q * S_PAD + kk];
            float e = (s > -1e29f) ? expf(s - mx) : 0.f;
            Ss[q * S_PAD + kk] = e;
            sum += e;
        }
        sum += __shfl_xor_sync(0xffffffffu, sum, 1);
        sum += __shfl_xor_sync(0xffffffffu, sum, 2);
        float inv = 1.f / sum;
        for (int kk = l; kk < 192; kk += 4) Ss[q * S_PAD + kk] *= inv;
    }
    __syncthreads();

    for (int idx = tid; idx < 64 * 16; idx += 256) {
        int q = idx >> 4, d4 = idx & 15;
        float4 acc = {0.f, 0.f, 0.f, 0.f};
        int kkend = q + 2 * CTX + 1;
        for (int kk = q; kk < kkend; kk++) {
            float p = Ss[q * S_PAD + kk];
            float4 v = *(const float4*)&Vs[kk * Q_PAD + d4 * 4];
            acc.x += p * v.x; acc.y += p * v.y; acc.z += p * v.z; acc.w += p * v.w;
        }
        __half2 h0 = __floats2half2_rn(acc.x, acc.y);
        __half2 h1 = __floats2half2_rn(acc.z, acc.w);
        __half2* p = (__half2*)(out + ((size_t)(b * TT + q0 + q)) * DIM + h * HD + d4 * 4);
        p[0] = h0; p[1] = h1;
    }
}

// ================= launcher =================
extern "C" void kernel_launch(void* const* d_in, const int* in_sizes, int n_in,
                              void* d_out, int out_size)
{
    const float* x       = (const float*)d_in[0];
    const float* norm1_w = (const float*)d_in[1];
    const float* norm2_w = (const float*)d_in[2];
    const float* w_qkv   = (const float*)d_in[3];
    const float* w_out   = (const float*)d_in[4];
    const float* b_out   = (const float*)d_in[5];
    const float* w1      = (const float*)d_in[6];
    const float* b1      = (const float*)d_in[7];
    const float* w2      = (const float*)d_in[8];
    const float* b2      = (const float*)d_in[9];
    float* y = (float*)d_out;

    __half *xn, *qkv, *attn, *hbuf, *wh;
    float *x1;
    cudaGetSymbolAddress((void**)&xn,   g_xn_h);
    cudaGetSymbolAddress((void**)&qkv,  g_qkv_h);
    cudaGetSymbolAddress((void**)&attn, g_attn_h);
    cudaGetSymbolAddress((void**)&hbuf, g_hbuf_h);
    cudaGetSymbolAddress((void**)&x1,   g_x1);
    cudaGetSymbolAddress((void**)&wh,   g_w_h);

    static_assert(SMEM_FLOATS * 4 <= 227 * 1024, "smem");
    cudaFuncSetAttribute(attn_kernel, cudaFuncAttributeMaxDynamicSharedMemorySize,
                         SMEM_FLOATS * 4);
    cudaFuncSetAttribute(gemm_h_kernel<0>, cudaFuncAttributeMaxDynamicSharedMemorySize, GEMM_SMEM);
    cudaFuncSetAttribute(gemm_h_kernel<1>, cudaFuncAttributeMaxDynamicSharedMemorySize, GEMM_SMEM);
    cudaFuncSetAttribute(gemm_h_kernel<2>, cudaFuncAttributeMaxDynamicSharedMemorySize, GEMM_SMEM);

    // 0. convert weights to fp16
    f2h_kernel<<<(3 * DIM * DIM / 4 + 255) / 256, 256>>>(w_qkv, wh + WQKV_OFF, 3 * DIM * DIM / 4);
    f2h_kernel<<<(DIM * DIM / 4 + 255) / 256, 256>>>(w_out, wh + WOUT_OFF, DIM * DIM / 4);
    f2h_kernel<<<(DIM * FFN / 4 + 255) / 256, 256>>>(w1, wh + W1_OFF, DIM * FFN / 4);
    f2h_kernel<<<(FFN * DIM / 4 + 255) / 256, 256>>>(w2, wh + W2_OFF, FFN * DIM / 4);

    // 1. rmsnorm(x) -> xn (half)
    rmsnorm_kernel<<<ROWS, 256>>>(x, norm1_w, xn);
    // 2. qkv = xn @ w_qkv (half out)
    gemm_h_kernel<0><<<dim3((3 * DIM) / 128, ROWS / 128), 128, GEMM_SMEM>>>(
        xn, wh + WQKV_OFF, nullptr, nullptr, qkv, 3 * DIM, DIM);
    // 3. banded attention -> attn (half)
    attn_kernel<<<dim3(TT / 64, NHEAD, BB), 256, SMEM_FLOATS * 4>>>(qkv, attn);
    // 4. x1 = x + attn @ w_out + b_out (float out)
    gemm_h_kernel<2><<<dim3(DIM / 128, ROWS / 128), 128, GEMM_SMEM>>>(
        attn, wh + WOUT_OFF, b_out, x, x1, DIM, DIM);
    // 5. rmsnorm(x1) -> xn (half)
    rmsnorm_kernel<<<ROWS, 256>>>(x1, norm2_w, xn);
    // 6. h = gelu(xn @ w1 + b1) (half out)
    gemm_h_kernel<1><<<dim3(FFN / 128, ROWS / 128), 128, GEMM_SMEM>>>(
        xn, wh + W1_OFF, b1, nullptr, hbuf, FFN, DIM);
    // 7. y = x1 + h @ w2 + b2 (float out)
    gemm_h_kernel<2><<<dim3(DIM / 128, ROWS / 128), 128, GEMM_SMEM>>>(
        hbuf, wh + W2_OFF, b2, x1, y, DIM, FFN);
}

// round 8
// speedup vs baseline: 4.0581x; 1.6401x over previous
#include <cuda_runtime.h>
#include <cuda_fp16.h>
#include <mma.h>
#include <math.h>
#include <stdint.h>

using namespace nvcuda;

#define DIM   512
#define NHEAD 8
#define HD    64
#define FFN   2048
#define BB    4
#define TT    2048
#define ROWS  (BB*TT)     // 8192
#define CTX   64

// ---------------- scratch (allocation-free) ----------------
__device__ __half g_xn_h  [ROWS * DIM];
__device__ __half g_qkv_h [ROWS * 3 * DIM];
__device__ __half g_attn_h[ROWS * DIM];
__device__ __half g_hbuf_h[ROWS * FFN];
__device__ float  g_x1    [ROWS * DIM];
// fp16 weights
#define WQKV_OFF 0
#define WOUT_OFF (3 * DIM * DIM)
#define W1_OFF   (WOUT_OFF + DIM * DIM)
#define W2_OFF   (W1_OFF + DIM * FFN)
#define WTOT     (W2_OFF + FFN * DIM)
__device__ __half g_w_h[WTOT];

// ================= helpers =================
__device__ __forceinline__ uint32_t smem_u32(const void* p) {
    uint32_t a;
    asm("{ .reg .u64 t; cvta.to.shared.u64 t, %1; cvt.u32.u64 %0, t; }" : "=r"(a) : "l"(p));
    return a;
}
__device__ __forceinline__ void cp_async16(uint32_t saddr, const void* gaddr) {
    asm volatile("cp.async.cg.shared.global [%0], [%1], 16;" :: "r"(saddr), "l"(gaddr));
}
#define CP_COMMIT() asm volatile("cp.async.commit_group;" ::: "memory")
#define CP_WAIT(n)  asm volatile("cp.async.wait_group %0;" :: "n"(n) : "memory")

// fp32 -> fp16 convert (weights)
__global__ void __launch_bounds__(256) f2h_kernel(
    const float* __restrict__ in, __half* __restrict__ out, int n4)
{
    int i = blockIdx.x * 256 + threadIdx.x;
    if (i < n4) {
        float4 v = ((const float4*)in)[i];
        __half2 h0 = __floats2half2_rn(v.x, v.y);
        __half2 h1 = __floats2half2_rn(v.z, v.w);
        ((__half2*)out)[i * 2]     = h0;
        ((__half2*)out)[i * 2 + 1] = h1;
    }
}

// ================= RMSNorm (half output) =================
__global__ void __launch_bounds__(256) rmsnorm_kernel(
    const float* __restrict__ x, const float* __restrict__ w, __half* __restrict__ y)
{
    int row = blockIdx.x;
    int t = threadIdx.x;
    const float* xr = x + (size_t)row * DIM;
    float v0 = xr[t], v1 = xr[t + 256];
    float s = v0 * v0 + v1 * v1;
    #pragma unroll
    for (int o = 16; o; o >>= 1) s += __shfl_xor_sync(0xffffffffu, s, o);
    __shared__ float red[8];
    if ((t & 31) == 0) red[t >> 5] = s;
    __syncthreads();
    if (t < 8) {
        float r = red[t];
        #pragma unroll
        for (int o = 4; o; o >>= 1) r += __shfl_xor_sync(0xffu, r, o);
        if (t == 0) red[0] = r;
    }
    __syncthreads();
    float inv = 1.0f / sqrtf(red[0] * (1.0f / DIM) + 1e-6f);
    __half* yr = y + (size_t)row * DIM;
    yr[t]       = __float2half_rn(v0 * inv * w[t]);
    yr[t + 256] = __float2half_rn(v1 * inv * w[t + 256]);
}

// ================= wmma fp16 GEMM, cp.async pipelined =================
#define KC     64
#define LDA    72
#define LDB    144
#define A_STG_H (128 * LDA)
#define B_STG_H (KC * LDB)
#define STG_H   (A_STG_H + B_STG_H)
#define LDST    136
#define GEMM_SMEM (2 * STG_H * 2)     // 73728 B

template<int EPI>
__global__ void __launch_bounds__(128, 2) gemm_h_kernel(
    const __half* __restrict__ A, const __half* __restrict__ Bg,
    const float* __restrict__ bias, const float* __restrict__ res,
    void* __restrict__ Cv, int N, int K)
{
    extern __shared__ char smraw[];
    __half* smh = (__half*)smraw;
    uint32_t sm_base = smem_u32(smraw);

    int tid = threadIdx.x;
    int wid = tid >> 5;
    int m0 = blockIdx.y * 128;
    int n0 = blockIdx.x * 128;
    int wm = wid >> 1;
    int wn = wid & 1;

    const int nc = K / KC;

    auto issue_chunk = [&](int ic) {
        uint32_t as_addr = sm_base + (uint32_t)((ic & 1) * STG_H) * 2;
        uint32_t bs_addr = as_addr + A_STG_H * 2;
        #pragma unroll
        for (int i = 0; i < 8; i++) {
            int task = tid + i * 128;
            int r = task >> 3, sg = task & 7;
            cp_async16(as_addr + (uint32_t)(r * LDA + sg * 8) * 2,
                       A + (size_t)(m0 + r) * K + ic * KC + sg * 8);
        }
        #pragma unroll
        for (int i = 0; i < 8; i++) {
            int task = tid + i * 128;
            int r = task >> 4, sg = task & 15;
            cp_async16(bs_addr + (uint32_t)(r * LDB + sg * 8) * 2,
                       Bg + (size_t)(ic * KC + r) * N + n0 + sg * 8);
        }
    };

    wmma::fragment<wmma::accumulator, 16, 16, 16, float> acc[4][4];
    #pragma unroll
    for (int i = 0; i < 4; i++)
        #pragma unroll
        for (int j = 0; j < 4; j++)
            wmma::fill_fragment(acc[i][j], 0.0f);

    issue_chunk(0); CP_COMMIT();

    for (int ic = 0; ic < nc; ic++) {
        if (ic + 1 < nc) { issue_chunk(ic + 1); CP_COMMIT(); CP_WAIT(1); }
        else             { CP_WAIT(0); }
        __syncthreads();

        __half* As = smh + (ic & 1) * STG_H;
        __half* Bs = As + A_STG_H;
        #pragma unroll
        for (int ks = 0; ks < 4; ks++) {
            wmma::fragment<wmma::matrix_a, 16, 16, 16, __half, wmma::row_major> af[4];
            wmma::fragment<wmma::matrix_b, 16, 16, 16, __half, wmma::row_major> bf[4];
            #pragma unroll
            for (int i = 0; i < 4; i++)
                wmma::load_matrix_sync(af[i], As + (size_t)(wm * 64 + i * 16) * LDA + ks * 16, LDA);
            #pragma unroll
            for (int j = 0; j < 4; j++)
                wmma::load_matrix_sync(bf[j], Bs + (size_t)(ks * 16) * LDB + wn * 64 + j * 16, LDB);
            #pragma unroll
            for (int i = 0; i < 4; i++)
                #pragma unroll
                for (int j = 0; j < 4; j++)
                    wmma::mma_sync(acc[i][j], af[i], bf[j], acc[i][j]);
        }
        __syncthreads();
    }

    float* stage = (float*)smraw;
    #pragma unroll
    for (int i = 0; i < 4; i++)
        #pragma unroll
        for (int j = 0; j < 4; j++)
            wmma::store_matrix_sync(stage + (size_t)(wm * 64 + i * 16) * LDST + wn * 64 + j * 16,
                                    acc[i][j], LDST, wmma::mem_row_major);
    __syncthreads();

    #pragma unroll
    for (int jj = 0; jj < 32; jj++) {
        int idx = jj * 128 + tid;
        int m = idx >> 5, g = idx & 31;
        float4 v = *(float4*)(stage + (size_t)m * LDST + g * 4);
        int c = n0 + g * 4;
        if (EPI == 2) {
            float4 b = *(const float4*)(bias + c);
            float4 rr = *(const float4*)(res + (size_t)(m0 + m) * N + c);
            v.x += b.x + rr.x; v.y += b.y + rr.y;
            v.z += b.z + rr.z; v.w += b.w + rr.w;
            *(float4*)((float*)Cv + (size_t)(m0 + m) * N + c) = v;
        } else {
            if (EPI == 1) {
                float4 b = *(const float4*)(bias + c);
                v.x += b.x; v.y += b.y; v.z += b.z; v.w += b.w;
                v.x = 0.5f * v.x * (1.0f + erff(v.x * 0.70710678118654752f));
                v.y = 0.5f * v.y * (1.0f + erff(v.y * 0.70710678118654752f));
                v.z = 0.5f * v.z * (1.0f + erff(v.z * 0.70710678118654752f));
                v.w = 0.5f * v.w * (1.0f + erff(v.w * 0.70710678118654752f));
            }
            __half2 h0 = __floats2half2_rn(v.x, v.y);
            __half2 h1 = __floats2half2_rn(v.z, v.w);
            __half2* p = (__half2*)((__half*)Cv + (size_t)(m0 + m) * N + c);
            p[0] = h0; p[1] = h1;
        }
    }
}

// ================= Banded attention, tensor-core =================
// One CTA per (b, h, 64-query tile), 256 threads (8 warps), keys window 192.
// QK^T and P@V via wmma fp16; softmax fp32 with index masking; 1/sum folded
// into output scale.
#define AQ_LD 72    // halves
#define AS_LD 200   // floats / halves (192 + 8)
#define AO_LD 72    // floats
// smem byte offsets
#define OFF_Q   0
#define OFF_K   (OFF_Q + 64 * AQ_LD * 2)
#define OFF_V   (OFF_K + 192 * AQ_LD * 2)
#define OFF_S   (OFF_V + 192 * AQ_LD * 2)            // floats
#define OFF_P   (OFF_S + 64 * AS_LD * 4)             // halves
#define OFF_INV (OFF_P + 64 * AS_LD * 2)             // 64 floats
#define ATTN_SMEM (OFF_INV + 64 * 4)

__global__ void __launch_bounds__(256) attn_kernel(
    const __half* __restrict__ qkv, __half* __restrict__ out)
{
    extern __shared__ char smraw[];
    __half* Qh = (__half*)(smraw + OFF_Q);
    __half* Kh = (__half*)(smraw + OFF_K);
    __half* Vh = (__half*)(smraw + OFF_V);
    float*  Sf = (float*) (smraw + OFF_S);
    __half* Ph = (__half*)(smraw + OFF_P);
    float*  Inv = (float*)(smraw + OFF_INV);

    int tid = threadIdx.x;
    int wid = tid >> 5;
    int qt = blockIdx.x, h = blockIdx.y, b = blockIdx.z;
    int q0 = qt * 64;
    int kbase = q0 - CTX;

    // ---- load Q (64 x 64 halves), K/V (192 x 64 halves, zero-filled OOB) ----
    for (int idx = tid; idx < 64 * 8; idx += 256) {
        int r = idx >> 3, d8 = idx & 7;
        uint4 v = *(const uint4*)(qkv + ((size_t)(b * TT + q0 + r)) * (3 * DIM) + h * HD + d8 * 8);
        *(uint4*)(Qh + r * AQ_LD + d8 * 8) = v;
    }
    for (int idx = tid; idx < 192 * 8; idx += 256) {
        int r = idx >> 3, d8 = idx & 7;
        int kg = kbase + r;
        uint4 kvv = {0, 0, 0, 0}, vvv = {0, 0, 0, 0};
        if (kg >= 0 && kg < TT) {
            const __half* base = qkv + ((size_t)(b * TT + kg)) * (3 * DIM) + h * HD + d8 * 8;
            kvv = *(const uint4*)(base + DIM);
            vvv = *(const uint4*)(base + 2 * DIM);
        }
        *(uint4*)(Kh + r * AQ_LD + d8 * 8) = kvv;
        *(uint4*)(Vh + r * AQ_LD + d8 * 8) = vvv;
    }
    __syncthreads();

    // ---- S = Q @ K^T : warp w -> rows (w&3)*16, cols ((w>>2)*6 .. +6)*16 ----
    {
        int rb = wid & 3;
        int cb0 = (wid >> 2) * 6;
        wmma::fragment<wmma::accumulator, 16, 16, 16, float> sacc[6];
        #pragma unroll
        for (int j = 0; j < 6; j++) wmma::fill_fragment(sacc[j], 0.0f);
        #pragma unroll
        for (int ks = 0; ks < 4; ks++) {
            wmma::fragment<wmma::matrix_a, 16, 16, 16, __half, wmma::row_major> aq;
            wmma::load_matrix_sync(aq, Qh + (size_t)(rb * 16) * AQ_LD + ks * 16, AQ_LD);
            #pragma unroll
            for (int j = 0; j < 6; j++) {
                wmma::fragment<wmma::matrix_b, 16, 16, 16, __half, wmma::col_major> bk;
                wmma::load_matrix_sync(bk, Kh + (size_t)((cb0 + j) * 16) * AQ_LD + ks * 16, AQ_LD);
                wmma::mma_sync(sacc[j], aq, bk, sacc[j]);
            }
        }
        #pragma unroll
        for (int j = 0; j < 6; j++)
            wmma::store_matrix_sync(Sf + (size_t)(rb * 16) * AS_LD + (cb0 + j) * 16,
                                    sacc[j], AS_LD, wmma::mem_row_major);
    }
    __syncthreads();

    // ---- masked softmax (fp32), P in half, 1/sum deferred to output ----
    {
        const float scale = 0.125f;
        int q = tid >> 2, l = tid & 3;
        float mx = -1e30f;
        #pragma unroll 4
        for (int kk = l; kk < 192; kk += 4) {
            int kg = kbase + kk;
            bool valid = (kk >= q) && (kk <= q + 2 * CTX) && (kg >= 0) && (kg < TT);
            float s = valid ? Sf[q * AS_LD + kk] * scale : -1e30f;
            mx = fmaxf(mx, s);
        }
        mx = fmaxf(mx, __shfl_xor_sync(0xffffffffu, mx, 1));
        mx = fmaxf(mx, __shfl_xor_sync(0xffffffffu, mx, 2));
        float sum = 0.f;
        #pragma unroll 4
        for (int kk = l; kk < 192; kk += 4) {
            int kg = kbase + kk;
            bool valid = (kk >= q) && (kk <= q + 2 * CTX) && (kg >= 0) && (kg < TT);
            float e = valid ? __expf(Sf[q * AS_LD + kk] * scale - mx) : 0.f;
            Ph[q * AS_LD + kk] = __float2half_rn(e);
            sum += e;
        }
        sum += __shfl_xor_sync(0xffffffffu, sum, 1);
        sum += __shfl_xor_sync(0xffffffffu, sum, 2);
        if (l == 0) Inv[q] = 1.0f / sum;
    }
    __syncthreads();

    // ---- O = P @ V : warp w -> rows (w&3)*16, cols ((w>>2)*2 .. +2)*16 ----
    {
        int rb = wid & 3;
        int cb0 = (wid >> 2) * 2;
        wmma::fragment<wmma::accumulator, 16, 16, 16, float> oacc[2];
        #pragma unroll
        for (int j = 0; j < 2; j++) wmma::fill_fragment(oacc[j], 0.0f);
        #pragma unroll
        for (int ks = 0; ks < 12; ks++) {
            wmma::fragment<wmma::matrix_a, 16, 16, 16, __half, wmma::row_major> ap;
            wmma::load_matrix_sync(ap, Ph + (size_t)(rb * 16) * AS_LD + ks * 16, AS_LD);
            #pragma unroll
            for (int j = 0; j < 2; j++) {
                wmma::fragment<wmma::matrix_b, 16, 16, 16, __half, wmma::row_major> bv;
                wmma::load_matrix_sync(bv, Vh + (size_t)(ks * 16) * AQ_LD + (cb0 + j) * 16, AQ_LD);
                wmma::mma_sync(oacc[j], ap, bv, oacc[j]);
            }
        }
        float* Of = Sf;   // reuse score region as 64 x AO_LD float stage
        #pragma unroll
        for (int j = 0; j < 2; j++)
            wmma::store_matrix_sync(Of + (size_t)(rb * 16) * AO_LD + (cb0 + j) * 16,
                                    oacc[j], AO_LD, wmma::mem_row_major);
    }
    __syncthreads();

    // ---- scale by Inv[q] and emit half ----
    {
        float* Of = Sf;
        for (int idx = tid; idx < 64 * 16; idx += 256) {
            int q = idx >> 4, d4 = idx & 15;
            float inv = Inv[q];
            float4 v = *(float4*)(Of + (size_t)q * AO_LD + d4 * 4);
            __half2 h0 = __floats2half2_rn(v.x * inv, v.y * inv);
            __half2 h1 = __floats2half2_rn(v.z * inv, v.w * inv);
            __half2* p = (__half2*)(out + ((size_t)(b * TT + q0 + q)) * DIM + h * HD + d4 * 4);
            p[0] = h0; p[1] = h1;
        }
    }
}

// ================= launcher =================
extern "C" void kernel_launch(void* const* d_in, const int* in_sizes, int n_in,
                              void* d_out, int out_size)
{
    const float* x       = (const float*)d_in[0];
    const float* norm1_w = (const float*)d_in[1];
    const float* norm2_w = (const float*)d_in[2];
    const float* w_qkv   = (const float*)d_in[3];
    const float* w_out   = (const float*)d_in[4];
    const float* b_out   = (const float*)d_in[5];
    const float* w1      = (const float*)d_in[6];
    const float* b1      = (const float*)d_in[7];
    const float* w2      = (const float*)d_in[8];
    const float* b2      = (const float*)d_in[9];
    float* y = (float*)d_out;

    __half *xn, *qkv, *attn, *hbuf, *wh;
    float *x1;
    cudaGetSymbolAddress((void**)&xn,   g_xn_h);
    cudaGetSymbolAddress((void**)&qkv,  g_qkv_h);
    cudaGetSymbolAddress((void**)&attn, g_attn_h);
    cudaGetSymbolAddress((void**)&hbuf, g_hbuf_h);
    cudaGetSymbolAddress((void**)&x1,   g_x1);
    cudaGetSymbolAddress((void**)&wh,   g_w_h);

    static_assert(ATTN_SMEM <= 227 * 1024, "attn smem");
    cudaFuncSetAttribute(attn_kernel, cudaFuncAttributeMaxDynamicSharedMemorySize, ATTN_SMEM);
    cudaFuncSetAttribute(gemm_h_kernel<0>, cudaFuncAttributeMaxDynamicSharedMemorySize, GEMM_SMEM);
    cudaFuncSetAttribute(gemm_h_kernel<1>, cudaFuncAttributeMaxDynamicSharedMemorySize, GEMM_SMEM);
    cudaFuncSetAttribute(gemm_h_kernel<2>, cudaFuncAttributeMaxDynamicSharedMemorySize, GEMM_SMEM);

    // 0. convert weights to fp16
    f2h_kernel<<<(3 * DIM * DIM / 4 + 255) / 256, 256>>>(w_qkv, wh + WQKV_OFF, 3 * DIM * DIM / 4);
    f2h_kernel<<<(DIM * DIM / 4 + 255) / 256, 256>>>(w_out, wh + WOUT_OFF, DIM * DIM / 4);
    f2h_kernel<<<(DIM * FFN / 4 + 255) / 256, 256>>>(w1, wh + W1_OFF, DIM * FFN / 4);
    f2h_kernel<<<(FFN * DIM / 4 + 255) / 256, 256>>>(w2, wh + W2_OFF, FFN * DIM / 4);

    // 1. rmsnorm(x) -> xn (half)
    rmsnorm_kernel<<<ROWS, 256>>>(x, norm1_w, xn);
    // 2. qkv = xn @ w_qkv (half out)
    gemm_h_kernel<0><<<dim3((3 * DIM) / 128, ROWS / 128), 128, GEMM_SMEM>>>(
        xn, wh + WQKV_OFF, nullptr, nullptr, qkv, 3 * DIM, DIM);
    // 3. banded attention (tensor-core) -> attn (half)
    attn_kernel<<<dim3(TT / 64, NHEAD, BB), 256, ATTN_SMEM>>>(qkv, attn);
    // 4. x1 = x + attn @ w_out + b_out (float out)
    gemm_h_kernel<2><<<dim3(DIM / 128, ROWS / 128), 128, GEMM_SMEM>>>(
        attn, wh + WOUT_OFF, b_out, x, x1, DIM, DIM);
    // 5. rmsnorm(x1) -> xn (half)
    rmsnorm_kernel<<<ROWS, 256>>>(x1, norm2_w, xn);
    // 6. h = gelu(xn @ w1 + b1) (half out)
    gemm_h_kernel<1><<<dim3(FFN / 128, ROWS / 128), 128, GEMM_SMEM>>>(
        xn, wh + W1_OFF, b1, nullptr, hbuf, FFN, DIM);
    // 7. y = x1 + h @ w2 + b2 (float out)
    gemm_h_kernel<2><<<dim3(DIM / 128, ROWS / 128), 128, GEMM_SMEM>>>(
        hbuf, wh + W2_OFF, b2, x1, y, DIM, FFN);
}

// round 9
// speedup vs baseline: 4.3156x; 1.0635x over previous
#include <cuda_runtime.h>
#include <cuda_fp16.h>
#include <mma.h>
#include <math.h>
#include <stdint.h>

using namespace nvcuda;

#define DIM   512
#define NHEAD 8
#define HD    64
#define FFN   2048
#define BB    4
#define TT    2048
#define ROWS  (BB*TT)     // 8192
#define CTX   64

// ---------------- scratch (allocation-free) ----------------
__device__ __half g_xn_h  [ROWS * DIM];
__device__ __half g_qkv_h [ROWS * 3 * DIM];
__device__ __half g_attn_h[ROWS * DIM];
__device__ __half g_hbuf_h[ROWS * FFN];
__device__ float  g_x1    [ROWS * DIM];
// fp16 weights
#define WQKV_OFF 0
#define WOUT_OFF (3 * DIM * DIM)                 // 786432
#define W1_OFF   (WOUT_OFF + DIM * DIM)          // 1048576
#define W2_OFF   (W1_OFF + DIM * FFN)            // 2097152
#define WTOT     (W2_OFF + FFN * DIM)            // 3145728
__device__ __half g_w_h[WTOT];

// ================= helpers =================
__device__ __forceinline__ uint32_t smem_u32(const void* p) {
    uint32_t a;
    asm("{ .reg .u64 t; cvta.to.shared.u64 t, %1; cvt.u32.u64 %0, t; }" : "=r"(a) : "l"(p));
    return a;
}
__device__ __forceinline__ void cp_async16(uint32_t saddr, const void* gaddr) {
    asm volatile("cp.async.cg.shared.global [%0], [%1], 16;" :: "r"(saddr), "l"(gaddr));
}
#define CP_COMMIT() asm volatile("cp.async.commit_group;" ::: "memory")
#define CP_WAIT(n)  asm volatile("cp.async.wait_group %0;" :: "n"(n) : "memory")

// ---- single fused fp32->fp16 weight convert ----
#define F4_QKV (3 * DIM * DIM / 4)           // 196608
#define F4_OUT (DIM * DIM / 4)               // 65536
#define F4_W1  (DIM * FFN / 4)               // 262144
#define F4_W2  (FFN * DIM / 4)               // 262144
#define F4_TOT (F4_QKV + F4_OUT + F4_W1 + F4_W2)   // 786432

__global__ void __launch_bounds__(256) f2h_all_kernel(
    const float* __restrict__ w_qkv, const float* __restrict__ w_out,
    const float* __restrict__ w1, const float* __restrict__ w2,
    __half* __restrict__ out)
{
    int i = blockIdx.x * 256 + threadIdx.x;
    if (i >= F4_TOT) return;
    const float* src;
    int rel;
    size_t dsth;  // half offset
    if (i < F4_QKV) {
        src = w_qkv; rel = i; dsth = WQKV_OFF;
    } else if (i < F4_QKV + F4_OUT) {
        src = w_out; rel = i - F4_QKV; dsth = WOUT_OFF;
    } else if (i < F4_QKV + F4_OUT + F4_W1) {
        src = w1; rel = i - F4_QKV - F4_OUT; dsth = W1_OFF;
    } else {
        src = w2; rel = i - F4_QKV - F4_OUT - F4_W1; dsth = W2_OFF;
    }
    float4 v = ((const float4*)src)[rel];
    __half2 h0 = __floats2half2_rn(v.x, v.y);
    __half2 h1 = __floats2half2_rn(v.z, v.w);
    __half2* p = (__half2*)(out + dsth) + rel * 2;
    p[0] = h0; p[1] = h1;
}

// ================= RMSNorm (half output) =================
__global__ void __launch_bounds__(256) rmsnorm_kernel(
    const float* __restrict__ x, const float* __restrict__ w, __half* __restrict__ y)
{
    int row = blockIdx.x;
    int t = threadIdx.x;
    const float* xr = x + (size_t)row * DIM;
    float v0 = xr[t], v1 = xr[t + 256];
    float s = v0 * v0 + v1 * v1;
    #pragma unroll
    for (int o = 16; o; o >>= 1) s += __shfl_xor_sync(0xffffffffu, s, o);
    __shared__ float red[8];
    if ((t & 31) == 0) red[t >> 5] = s;
    __syncthreads();
    if (t < 8) {
        float r = red[t];
        #pragma unroll
        for (int o = 4; o; o >>= 1) r += __shfl_xor_sync(0xffu, r, o);
        if (t == 0) red[0] = r;
    }
    __syncthreads();
    float inv = 1.0f / sqrtf(red[0] * (1.0f / DIM) + 1e-6f);
    __half* yr = y + (size_t)row * DIM;
    yr[t]       = __float2half_rn(v0 * inv * w[t]);
    yr[t + 256] = __float2half_rn(v1 * inv * w[t + 256]);
}

// ================= wmma fp16 GEMM, cp.async pipelined =================
#define KC     64
#define LDA    72
#define LDB    144
#define A_STG_H (128 * LDA)
#define B_STG_H (KC * LDB)
#define STG_H   (A_STG_H + B_STG_H)
#define LDST    136
#define GEMM_SMEM (2 * STG_H * 2)     // 73728 B

template<int EPI>
__global__ void __launch_bounds__(128, 2) gemm_h_kernel(
    const __half* __restrict__ A, const __half* __restrict__ Bg,
    const float* __restrict__ bias, const float* __restrict__ res,
    void* __restrict__ Cv, int N, int K)
{
    extern __shared__ char smraw[];
    __half* smh = (__half*)smraw;
    uint32_t sm_base = smem_u32(smraw);

    int tid = threadIdx.x;
    int wid = tid >> 5;
    int m0 = blockIdx.y * 128;
    int n0 = blockIdx.x * 128;
    int wm = wid >> 1;
    int wn = wid & 1;

    const int nc = K / KC;

    auto issue_chunk = [&](int ic) {
        uint32_t as_addr = sm_base + (uint32_t)((ic & 1) * STG_H) * 2;
        uint32_t bs_addr = as_addr + A_STG_H * 2;
        #pragma unroll
        for (int i = 0; i < 8; i++) {
            int task = tid + i * 128;
            int r = task >> 3, sg = task & 7;
            cp_async16(as_addr + (uint32_t)(r * LDA + sg * 8) * 2,
                       A + (size_t)(m0 + r) * K + ic * KC + sg * 8);
        }
        #pragma unroll
        for (int i = 0; i < 8; i++) {
            int task = tid + i * 128;
            int r = task >> 4, sg = task & 15;
            cp_async16(bs_addr + (uint32_t)(r * LDB + sg * 8) * 2,
                       Bg + (size_t)(ic * KC + r) * N + n0 + sg * 8);
        }
    };

    wmma::fragment<wmma::accumulator, 16, 16, 16, float> acc[4][4];
    #pragma unroll
    for (int i = 0; i < 4; i++)
        #pragma unroll
        for (int j = 0; j < 4; j++)
            wmma::fill_fragment(acc[i][j], 0.0f);

    issue_chunk(0); CP_COMMIT();

    for (int ic = 0; ic < nc; ic++) {
        if (ic + 1 < nc) { issue_chunk(ic + 1); CP_COMMIT(); CP_WAIT(1); }
        else             { CP_WAIT(0); }
        __syncthreads();

        __half* As = smh + (ic & 1) * STG_H;
        __half* Bs = As + A_STG_H;
        #pragma unroll
        for (int ks = 0; ks < 4; ks++) {
            wmma::fragment<wmma::matrix_a, 16, 16, 16, __half, wmma::row_major> af[4];
            wmma::fragment<wmma::matrix_b, 16, 16, 16, __half, wmma::row_major> bf[4];
            #pragma unroll
            for (int i = 0; i < 4; i++)
                wmma::load_matrix_sync(af[i], As + (size_t)(wm * 64 + i * 16) * LDA + ks * 16, LDA);
            #pragma unroll
            for (int j = 0; j < 4; j++)
                wmma::load_matrix_sync(bf[j], Bs + (size_t)(ks * 16) * LDB + wn * 64 + j * 16, LDB);
            #pragma unroll
            for (int i = 0; i < 4; i++)
                #pragma unroll
                for (int j = 0; j < 4; j++)
                    wmma::mma_sync(acc[i][j], af[i], bf[j], acc[i][j]);
        }
        __syncthreads();
    }

    float* stage = (float*)smraw;
    #pragma unroll
    for (int i = 0; i < 4; i++)
        #pragma unroll
        for (int j = 0; j < 4; j++)
            wmma::store_matrix_sync(stage + (size_t)(wm * 64 + i * 16) * LDST + wn * 64 + j * 16,
                                    acc[i][j], LDST, wmma::mem_row_major);
    __syncthreads();

    #pragma unroll
    for (int jj = 0; jj < 32; jj++) {
        int idx = jj * 128 + tid;
        int m = idx >> 5, g = idx & 31;
        float4 v = *(float4*)(stage + (size_t)m * LDST + g * 4);
        int c = n0 + g * 4;
        if (EPI == 2) {
            float4 b = *(const float4*)(bias + c);
            float4 rr = *(const float4*)(res + (size_t)(m0 + m) * N + c);
            v.x += b.x + rr.x; v.y += b.y + rr.y;
            v.z += b.z + rr.z; v.w += b.w + rr.w;
            *(float4*)((float*)Cv + (size_t)(m0 + m) * N + c) = v;
        } else {
            if (EPI == 1) {
                float4 b = *(const float4*)(bias + c);
                v.x += b.x; v.y += b.y; v.z += b.z; v.w += b.w;
                v.x = 0.5f * v.x * (1.0f + erff(v.x * 0.70710678118654752f));
                v.y = 0.5f * v.y * (1.0f + erff(v.y * 0.70710678118654752f));
                v.z = 0.5f * v.z * (1.0f + erff(v.z * 0.70710678118654752f));
                v.w = 0.5f * v.w * (1.0f + erff(v.w * 0.70710678118654752f));
            }
            __half2 h0 = __floats2half2_rn(v.x, v.y);
            __half2 h1 = __floats2half2_rn(v.z, v.w);
            __half2* p = (__half2*)((__half*)Cv + (size_t)(m0 + m) * N + c);
            p[0] = h0; p[1] = h1;
        }
    }
}

// ================= Banded attention, tensor-core, 2 CTAs/SM =================
// One CTA per (b, h, 64-query tile), 256 threads (8 warps), keys window 192.
// V loads into the (dead) Q+K region after softmax -> smem 110.3 KB -> occ 2.
#define AQ_LD 72    // halves
#define AS_LD 196   // floats (192 + 4), mult of 4
#define AP_LD 200   // halves (rows 16B-aligned)
#define AO_LD 72    // floats
#define AT_Q   0
#define AT_K   (AT_Q + 64 * AQ_LD * 2)               // 9216
#define AT_V   0                                      // overlays Q+K (27648 <= 36864)
#define AT_S   (AT_K + 192 * AQ_LD * 2)              // 36864, floats
#define AT_P   (AT_S + 64 * AS_LD * 4)               // 87040, halves
#define AT_I   (AT_P + 64 * AP_LD * 2)               // 112640
#define ATTN_SMEM (AT_I + 64 * 4)                    // 112896 B

__global__ void __launch_bounds__(256, 2) attn_kernel(
    const __half* __restrict__ qkv, __half* __restrict__ out)
{
    extern __shared__ char smraw[];
    __half* Qh = (__half*)(smraw + AT_Q);
    __half* Kh = (__half*)(smraw + AT_K);
    __half* Vh = (__half*)(smraw + AT_V);
    float*  Sf = (float*) (smraw + AT_S);
    __half* Ph = (__half*)(smraw + AT_P);
    float*  Inv = (float*)(smraw + AT_I);

    int tid = threadIdx.x;
    int wid = tid >> 5;
    int qt = blockIdx.x, h = blockIdx.y, b = blockIdx.z;
    int q0 = qt * 64;
    int kbase = q0 - CTX;

    // ---- load Q (64x64 halves) and K (192x64 halves, zero-filled OOB) ----
    for (int idx = tid; idx < 64 * 8; idx += 256) {
        int r = idx >> 3, d8 = idx & 7;
        uint4 v = *(const uint4*)(qkv + ((size_t)(b * TT + q0 + r)) * (3 * DIM) + h * HD + d8 * 8);
        *(uint4*)(Qh + r * AQ_LD + d8 * 8) = v;
    }
    for (int idx = tid; idx < 192 * 8; idx += 256) {
        int r = idx >> 3, d8 = idx & 7;
        int kg = kbase + r;
        uint4 kvv = {0, 0, 0, 0};
        if (kg >= 0 && kg < TT)
            kvv = *(const uint4*)(qkv + ((size_t)(b * TT + kg)) * (3 * DIM) + h * HD + DIM + d8 * 8);
        *(uint4*)(Kh + r * AQ_LD + d8 * 8) = kvv;
    }
    __syncthreads();

    // ---- S = Q @ K^T : warp w -> rows (w&3)*16, col-blocks (w>>2)*6 .. +6 ----
    {
        int rb = wid & 3;
        int cb0 = (wid >> 2) * 6;
        wmma::fragment<wmma::accumulator, 16, 16, 16, float> sacc[6];
        #pragma unroll
        for (int j = 0; j < 6; j++) wmma::fill_fragment(sacc[j], 0.0f);
        #pragma unroll
        for (int ks = 0; ks < 4; ks++) {
            wmma::fragment<wmma::matrix_a, 16, 16, 16, __half, wmma::row_major> aq;
            wmma::load_matrix_sync(aq, Qh + (size_t)(rb * 16) * AQ_LD + ks * 16, AQ_LD);
            #pragma unroll
            for (int j = 0; j < 6; j++) {
                wmma::fragment<wmma::matrix_b, 16, 16, 16, __half, wmma::col_major> bk;
                wmma::load_matrix_sync(bk, Kh + (size_t)((cb0 + j) * 16) * AQ_LD + ks * 16, AQ_LD);
                wmma::mma_sync(sacc[j], aq, bk, sacc[j]);
            }
        }
        #pragma unroll
        for (int j = 0; j < 6; j++)
            wmma::store_matrix_sync(Sf + (size_t)(rb * 16) * AS_LD + (cb0 + j) * 16,
                                    sacc[j], AS_LD, wmma::mem_row_major);
    }
    __syncthreads();

    // ---- masked softmax (fp32), P in half, 1/sum deferred to output ----
    {
        const float scale = 0.125f;
        int q = tid >> 2, l = tid & 3;
        float mx = -1e30f;
        #pragma unroll 4
        for (int kk = l; kk < 192; kk += 4) {
            int kg = kbase + kk;
            bool valid = (kk >= q) && (kk <= q + 2 * CTX) && (kg >= 0) && (kg < TT);
            float s = valid ? Sf[q * AS_LD + kk] * scale : -1e30f;
            mx = fmaxf(mx, s);
        }
        mx = fmaxf(mx, __shfl_xor_sync(0xffffffffu, mx, 1));
        mx = fmaxf(mx, __shfl_xor_sync(0xffffffffu, mx, 2));
        float sum = 0.f;
        #pragma unroll 4
        for (int kk = l; kk < 192; kk += 4) {
            int kg = kbase + kk;
            bool valid = (kk >= q) && (kk <= q + 2 * CTX) && (kg >= 0) && (kg < TT);
            float e = valid ? __expf(Sf[q * AS_LD + kk] * scale - mx) : 0.f;
            Ph[q * AP_LD + kk] = __float2half_rn(e);
            sum += e;
        }
        sum += __shfl_xor_sync(0xffffffffu, sum, 1);
        sum += __shfl_xor_sync(0xffffffffu, sum, 2);
        if (l == 0) Inv[q] = 1.0f / sum;
    }
    __syncthreads();

    // ---- load V into the dead Q+K region ----
    for (int idx = tid; idx < 192 * 8; idx += 256) {
        int r = idx >> 3, d8 = idx & 7;
        int kg = kbase + r;
        uint4 vvv = {0, 0, 0, 0};
        if (kg >= 0 && kg < TT)
            vvv = *(const uint4*)(qkv + ((size_t)(b * TT + kg)) * (3 * DIM) + h * HD + 2 * DIM + d8 * 8);
        *(uint4*)(Vh + r * AQ_LD + d8 * 8) = vvv;
    }
    __syncthreads();

    // ---- O = P @ V : warp w -> rows (w&3)*16, col-blocks (w>>2)*2 .. +2 ----
    {
        int rb = wid & 3;
        int cb0 = (wid >> 2) * 2;
        wmma::fragment<wmma::accumulator, 16, 16, 16, float> oacc[2];
        #pragma unroll
        for (int j = 0; j < 2; j++) wmma::fill_fragment(oacc[j], 0.0f);
        #pragma unroll
        for (int ks = 0; ks < 12; ks++) {
            wmma::fragment<wmma::matrix_a, 16, 16, 16, __half, wmma::row_major> ap;
            wmma::load_matrix_sync(ap, Ph + (size_t)(rb * 16) * AP_LD + ks * 16, AP_LD);
            #pragma unroll
            for (int j = 0; j < 2; j++) {
                wmma::fragment<wmma::matrix_b, 16, 16, 16, __half, wmma::row_major> bv;
                wmma::load_matrix_sync(bv, Vh + (size_t)(ks * 16) * AQ_LD + (cb0 + j) * 16, AQ_LD);
                wmma::mma_sync(oacc[j], ap, bv, oacc[j]);
            }
        }
        float* Of = Sf;   // reuse score region as 64 x AO_LD float stage
        #pragma unroll
        for (int j = 0; j < 2; j++)
            wmma::store_matrix_sync(Of + (size_t)(rb * 16) * AO_LD + (cb0 + j) * 16,
                                    oacc[j], AO_LD, wmma::mem_row_major);
    }
    __syncthreads();

    // ---- scale by Inv[q] and emit half ----
    {
        float* Of = Sf;
        for (int idx = tid; idx < 64 * 16; idx += 256) {
            int q = idx >> 4, d4 = idx & 15;
            float inv = Inv[q];
            float4 v = *(float4*)(Of + (size_t)q * AO_LD + d4 * 4);
            __half2 h0 = __floats2half2_rn(v.x * inv, v.y * inv);
            __half2 h1 = __floats2half2_rn(v.z * inv, v.w * inv);
            __half2* p = (__half2*)(out + ((size_t)(b * TT + q0 + q)) * DIM + h * HD + d4 * 4);
            p[0] = h0; p[1] = h1;
        }
    }
}

// ================= launcher =================
extern "C" void kernel_launch(void* const* d_in, const int* in_sizes, int n_in,
                              void* d_out, int out_size)
{
    const float* x       = (const float*)d_in[0];
    const float* norm1_w = (const float*)d_in[1];
    const float* norm2_w = (const float*)d_in[2];
    const float* w_qkv   = (const float*)d_in[3];
    const float* w_out   = (const float*)d_in[4];
    const float* b_out   = (const float*)d_in[5];
    const float* w1      = (const float*)d_in[6];
    const float* b1      = (const float*)d_in[7];
    const float* w2      = (const float*)d_in[8];
    const float* b2      = (const float*)d_in[9];
    float* y = (float*)d_out;

    __half *xn, *qkv, *attn, *hbuf, *wh;
    float *x1;
    cudaGetSymbolAddress((void**)&xn,   g_xn_h);
    cudaGetSymbolAddress((void**)&qkv,  g_qkv_h);
    cudaGetSymbolAddress((void**)&attn, g_attn_h);
    cudaGetSymbolAddress((void**)&hbuf, g_hbuf_h);
    cudaGetSymbolAddress((void**)&x1,   g_x1);
    cudaGetSymbolAddress((void**)&wh,   g_w_h);

    static_assert(ATTN_SMEM <= 113 * 1024, "attn smem must allow 2 CTAs/SM");
    cudaFuncSetAttribute(attn_kernel, cudaFuncAttributeMaxDynamicSharedMemorySize, ATTN_SMEM);
    cudaFuncSetAttribute(gemm_h_kernel<0>, cudaFuncAttributeMaxDynamicSharedMemorySize, GEMM_SMEM);
    cudaFuncSetAttribute(gemm_h_kernel<1>, cudaFuncAttributeMaxDynamicSharedMemorySize, GEMM_SMEM);
    cudaFuncSetAttribute(gemm_h_kernel<2>, cudaFuncAttributeMaxDynamicSharedMemorySize, GEMM_SMEM);

    // 0. convert all weights to fp16 (one launch)
    f2h_all_kernel<<<(F4_TOT + 255) / 256, 256>>>(w_qkv, w_out, w1, w2, wh);

    // 1. rmsnorm(x) -> xn (half)
    rmsnorm_kernel<<<ROWS, 256>>>(x, norm1_w, xn);
    // 2. qkv = xn @ w_qkv (half out)
    gemm_h_kernel<0><<<dim3((3 * DIM) / 128, ROWS / 128), 128, GEMM_SMEM>>>(
        xn, wh + WQKV_OFF, nullptr, nullptr, qkv, 3 * DIM, DIM);
    // 3. banded attention (tensor-core, occ 2) -> attn (half)
    attn_kernel<<<dim3(TT / 64, NHEAD, BB), 256, ATTN_SMEM>>>(qkv, attn);
    // 4. x1 = x + attn @ w_out + b_out (float out)
    gemm_h_kernel<2><<<dim3(DIM / 128, ROWS / 128), 128, GEMM_SMEM>>>(
        attn, wh + WOUT_OFF, b_out, x, x1, DIM, DIM);
    // 5. rmsnorm(x1) -> xn (half)
    rmsnorm_kernel<<<ROWS, 256>>>(x1, norm2_w, xn);
    // 6. h = gelu(xn @ w1 + b1) (half out)
    gemm_h_kernel<1><<<dim3(FFN / 128, ROWS / 128), 128, GEMM_SMEM>>>(
        xn, wh + W1_OFF, b1, nullptr, hbuf, FFN, DIM);
    // 7. y = x1 + h @ w2 + b2 (float out)
    gemm_h_kernel<2><<<dim3(DIM / 128, ROWS / 128), 128, GEMM_SMEM>>>(
        hbuf, wh + W2_OFF, b2, x1, y, DIM, FFN);
}